// round 2
// baseline (speedup 1.0000x reference)
#include <cuda_runtime.h>
#include <math.h>

#define NN 100000
#define DD 200
#define EE 400000
#define GG 600   // 3*DD
#define IND 100

// ---------------- scratch (static device globals; no allocation) ----------------
__device__ float g_h0[NN * DD];
__device__ float g_h1[NN * DD];
__device__ float g_m[NN * DD];
__device__ float g_aggr[NN * DD];
__device__ float g_gi[NN * GG];
__device__ float g_gh[NN * GG];
__device__ float g_pooled[256];
__device__ int   g_is64;

// ---------------- edge dtype detect: int64 little-endian small values have all
// odd 32-bit words == 0. int32 node ids in [0,100000) make that impossible
// across 1000 samples (p ~ 1e-5000). ----------------
__global__ void k_detect(const int* __restrict__ ei_words) {
    int any = 0;
    for (int i = 1; i < 2000; i += 2) any |= ei_words[i];
    g_is64 = (any == 0) ? 1 : 0;
}

// ---------------- init: h = pad(x), zero pooled ----------------
__global__ void k_init(const float* __restrict__ x) {
    int gid = blockIdx.x * blockDim.x + threadIdx.x;
    if (gid < 256) g_pooled[gid] = 0.0f;
    if (gid >= NN * DD) return;
    int n = gid / DD, d = gid % DD;
    g_h0[gid] = (d < IND) ? x[n * IND + d] : 0.0f;
}

// ---------------- tiled GEMM: C[N x P] = A[N x 200] * op(B) (+bias) ----------------
// op(B)[k][p] = BT ? B[p*200+k] : B[k*P+p]
// tile: 64 rows x 64 cols, 256 threads, 4x4 micro-tile, K=200 in 4 chunks of 50.
template <bool BT>
__global__ void __launch_bounds__(256)
k_gemm(const float* __restrict__ A, const float* __restrict__ B,
       const float* __restrict__ bias, float* __restrict__ C, int P) {
    extern __shared__ float sm[];
    float* As = sm;               // [50][68]   (k-major, padded)
    float* Bs = sm + 50 * 68;     // [200][68]  (k-major, padded)

    const int row0 = blockIdx.x * 64;
    const int col0 = blockIdx.y * 64;
    const int tid  = threadIdx.x;

    // load full B tile (64 cols x 200 k) once
    for (int idx = tid; idx < 64 * 200; idx += 256) {
        int p, k;
        if (BT) { p = idx / 200; k = idx % 200; }
        else    { k = idx / 64;  p = idx % 64;  }
        int gp = col0 + p;
        float v = 0.0f;
        if (gp < P) v = BT ? B[gp * 200 + k] : B[k * P + gp];
        Bs[k * 68 + p] = v;
    }

    float acc[4][4] = {};
    const int tr = tid & 15;   // row quad: rows 4*tr..+3
    const int tc = tid >> 4;   // col quad: cols 4*tc..+3

    for (int kc = 0; kc < 4; kc++) {
        __syncthreads();
        // load A chunk (64 rows x 50 k), transposed into smem
        for (int idx = tid; idx < 64 * 50; idx += 256) {
            int r = idx / 50, kk = idx % 50;
            int gr = row0 + r;
            As[kk * 68 + r] = (gr < NN) ? A[gr * 200 + kc * 50 + kk] : 0.0f;
        }
        __syncthreads();
#pragma unroll 10
        for (int kk = 0; kk < 50; kk++) {
            float4 a4 = *(const float4*)&As[kk * 68 + 4 * tr];
            float4 b4 = *(const float4*)&Bs[(kc * 50 + kk) * 68 + 4 * tc];
            acc[0][0] += a4.x * b4.x; acc[0][1] += a4.x * b4.y;
            acc[0][2] += a4.x * b4.z; acc[0][3] += a4.x * b4.w;
            acc[1][0] += a4.y * b4.x; acc[1][1] += a4.y * b4.y;
            acc[1][2] += a4.y * b4.z; acc[1][3] += a4.y * b4.w;
            acc[2][0] += a4.z * b4.x; acc[2][1] += a4.z * b4.y;
            acc[2][2] += a4.z * b4.z; acc[2][3] += a4.z * b4.w;
            acc[3][0] += a4.w * b4.x; acc[3][1] += a4.w * b4.y;
            acc[3][2] += a4.w * b4.z; acc[3][3] += a4.w * b4.w;
        }
    }

#pragma unroll
    for (int i = 0; i < 4; i++) {
        int gr = row0 + 4 * tr + i;
        if (gr >= NN) continue;
#pragma unroll
        for (int j = 0; j < 4; j++) {
            int gp = col0 + 4 * tc + j;
            if (gp < P) {
                float v = acc[i][j];
                if (bias) v += bias[gp];
                C[gr * P + gp] = v;
            }
        }
    }
}

// ---------------- edge scatter-add: aggr[dst] += m[src] ----------------
__global__ void k_scatter(const int* __restrict__ ei) {
    int gid = blockIdx.x * blockDim.x + threadIdx.x;
    if (gid >= EE * 50) return;
    int e = gid / 50;
    int q = gid % 50;                 // 4-float quad within the 200-dim row
    int src, dst;
    if (g_is64) {                     // int64 buffer: take low words
        src = ei[2 * e];
        dst = ei[2 * (EE + e)];
    } else {                          // int32 buffer
        src = ei[e];
        dst = ei[EE + e];
    }
    float4 v = *(const float4*)&g_m[src * DD + 4 * q];
    float* a = &g_aggr[dst * DD + 4 * q];
    atomicAdd(a + 0, v.x);
    atomicAdd(a + 1, v.y);
    atomicAdd(a + 2, v.z);
    atomicAdd(a + 3, v.w);
}

// ---------------- GRU elementwise ----------------
__device__ __forceinline__ float sigmoidf_(float x) { return 1.0f / (1.0f + expf(-x)); }

__global__ void k_gru(const float* __restrict__ hprev, float* __restrict__ hnext) {
    int gid = blockIdx.x * blockDim.x + threadIdx.x;
    if (gid >= NN * DD) return;
    int n = gid / DD, d = gid % DD;
    const float* gi = g_gi + n * GG;
    const float* gh = g_gh + n * GG;
    float r  = sigmoidf_(gi[d]          + gh[d]);
    float z  = sigmoidf_(gi[DD + d]     + gh[DD + d]);
    float nn = tanhf(gi[2 * DD + d] + r * gh[2 * DD + d]);
    float h  = hprev[gid];
    hnext[gid] = (1.0f - z) * nn + z * h;
}

// ---------------- relu + global max-pool ----------------
__global__ void k_pool(const float* __restrict__ h) {
    int d = threadIdx.x;
    if (d >= DD) return;
    int n0 = blockIdx.x * 500;
    int n1 = n0 + 500; if (n1 > NN) n1 = NN;
    float v = 0.0f;   // relu floor
    for (int n = n0; n < n1; n++) v = fmaxf(v, h[n * DD + d]);
    atomicMax((int*)&g_pooled[d], __float_as_int(v));  // v >= 0: int order == float order
}

// ---------------- classifier + softmax ----------------
__global__ void k_final(const float* __restrict__ cls_w, const float* __restrict__ cls_b,
                        float* __restrict__ out) {
    int lane = threadIdx.x;
    float l0 = 0.0f, l1 = 0.0f;
    for (int d = lane; d < DD; d += 32) {
        float p = g_pooled[d];
        l0 += p * cls_w[d];
        l1 += p * cls_w[DD + d];
    }
#pragma unroll
    for (int o = 16; o; o >>= 1) {
        l0 += __shfl_xor_sync(0xFFFFFFFF, l0, o);
        l1 += __shfl_xor_sync(0xFFFFFFFF, l1, o);
    }
    if (lane == 0) {
        l0 += cls_b[0];
        l1 += cls_b[1];
        float mx = fmaxf(l0, l1);
        float e0 = expf(l0 - mx), e1 = expf(l1 - mx);
        float s = e0 + e1;
        out[0] = e0 / s;
        out[1] = e1 / s;
    }
}

// ---------------- launch ----------------
extern "C" void kernel_launch(void* const* d_in, const int* in_sizes, int n_in,
                              void* d_out, int out_size) {
    const float* x     = (const float*)d_in[0];
    const float* W     = (const float*)d_in[1];
    const float* w_ih  = (const float*)d_in[2];
    const float* w_hh  = (const float*)d_in[3];
    const float* b_ih  = (const float*)d_in[4];
    const float* b_hh  = (const float*)d_in[5];
    const float* cls_w = (const float*)d_in[6];
    const float* cls_b = (const float*)d_in[7];
    const int*   ei    = (const int*)d_in[8];
    float*       out   = (float*)d_out;

    const size_t smem = (50 * 68 + 200 * 68) * sizeof(float);  // 68000 B
    cudaFuncSetAttribute(k_gemm<false>, cudaFuncAttributeMaxDynamicSharedMemorySize, (int)smem);
    cudaFuncSetAttribute(k_gemm<true>,  cudaFuncAttributeMaxDynamicSharedMemorySize, (int)smem);

    float *h0, *h1, *mp, *aggr, *gi, *gh;
    cudaGetSymbolAddress((void**)&h0,   g_h0);
    cudaGetSymbolAddress((void**)&h1,   g_h1);
    cudaGetSymbolAddress((void**)&mp,   g_m);
    cudaGetSymbolAddress((void**)&aggr, g_aggr);
    cudaGetSymbolAddress((void**)&gi,   g_gi);
    cudaGetSymbolAddress((void**)&gh,   g_gh);
    float* hb[2] = {h0, h1};

    k_detect<<<1, 1>>>(ei);
    k_init<<<(NN * DD + 255) / 256, 256>>>(x);

    const int rowBlocks = (NN + 63) / 64;   // 1563
    dim3 gridM(rowBlocks, (DD + 63) / 64);  // x4
    dim3 gridG(rowBlocks, (GG + 63) / 64);  // x10

    for (int s = 0; s < 4; s++) {
        float* hcur = hb[s & 1];
        float* hnxt = hb[(s + 1) & 1];
        cudaMemsetAsync(aggr, 0, (size_t)NN * DD * sizeof(float));
        k_gemm<false><<<gridM, 256, smem>>>(hcur, W + (size_t)s * DD * DD, nullptr, mp, DD);
        k_scatter<<<(EE * 50 + 255) / 256, 256>>>(ei);
        k_gemm<true><<<gridG, 256, smem>>>(hcur, w_hh, b_hh, gh, GG);
        k_gemm<true><<<gridG, 256, smem>>>(aggr, w_ih, b_ih, gi, GG);
        k_gru<<<(NN * DD + 255) / 256, 256>>>(hcur, hnxt);
    }

    k_pool<<<(NN + 499) / 500, 256>>>(hb[0]);  // after 4 steps, h is back in h0
    k_final<<<1, 32>>>(cls_w, cls_b, out);
}

// round 9
// speedup vs baseline: 2.4470x; 2.4470x over previous
#include <cuda_runtime.h>
#include <cuda_bf16.h>
#include <math.h>
#include <stdint.h>

#define NN 100000
#define DD 200
#define EE 400000
#define GG 600
#define IND 100

// ---------------- scratch (static device globals; no allocation) ----------------
__device__ float g_h0[NN * DD];
__device__ float g_h1[NN * DD];
__device__ float g_m[NN * DD];
__device__ float g_aggr[NN * DD];
__device__ float g_gi[NN * GG];
__device__ float g_gh[NN * GG];
__device__ float g_pooled[256];
__device__ int   g_is64;

// Packed bf16 activations: [NN][104] u32 (208 bf16 cols, k-pad zero). hi/lo split.
__device__ uint32_t g_Ahi[NN * 104];
__device__ uint32_t g_Alo[NN * 104];

// Weight images [n][k]: k contiguous (bf16 pairs as u32), 104 u32 per row (208 k, pad 0).
// B1: per step, 832 n-rows (cols 0..199 = W_s for m; 200..799 = w_hh; pad).
__device__ uint32_t g_B1hi[4 * 832 * 104];
__device__ uint32_t g_B1lo[4 * 832 * 104];
__device__ uint32_t g_B2hi[640 * 104];
__device__ uint32_t g_B2lo[640 * 104];
__device__ float    g_bias1[832];
__device__ float    g_bias2[640];

// ---------------- small helpers ----------------
__device__ __forceinline__ void split_pair(float v0, float v1, uint32_t& hi, uint32_t& lo) {
    __nv_bfloat16 h0 = __float2bfloat16(v0), h1 = __float2bfloat16(v1);
    float r0 = v0 - __bfloat162float(h0), r1 = v1 - __bfloat162float(h1);
    __nv_bfloat16 l0 = __float2bfloat16(r0), l1 = __float2bfloat16(r1);
    hi = (uint32_t)__bfloat16_as_ushort(h0) | ((uint32_t)__bfloat16_as_ushort(h1) << 16);
    lo = (uint32_t)__bfloat16_as_ushort(l0) | ((uint32_t)__bfloat16_as_ushort(l1) << 16);
}
__device__ __forceinline__ uint32_t smem_u32(const void* p) {
    uint32_t a;
    asm("{ .reg .u64 t; cvta.to.shared.u64 t, %1; cvt.u32.u64 %0, t; }" : "=r"(a) : "l"(p));
    return a;
}

#define LDSM_X4(r0, r1, r2, r3, addr) \
    asm volatile("ldmatrix.sync.aligned.m8n8.x4.shared.b16 {%0,%1,%2,%3}, [%4];" \
                 : "=r"(r0), "=r"(r1), "=r"(r2), "=r"(r3) : "r"(addr))

#define MMA_BF16(d, a, b) \
    asm volatile("mma.sync.aligned.m16n8k16.row.col.f32.bf16.bf16.f32 " \
                 "{%0,%1,%2,%3}, {%4,%5,%6,%7}, {%8,%9}, {%0,%1,%2,%3};" \
                 : "+f"((d)[0]), "+f"((d)[1]), "+f"((d)[2]), "+f"((d)[3]) \
                 : "r"((a)[0]), "r"((a)[1]), "r"((a)[2]), "r"((a)[3]), \
                   "r"((b)[0]), "r"((b)[1]))

// ---------------- edge dtype detect ----------------
__global__ void k_detect(const int* __restrict__ w) {
    int any = 0;
    for (int i = 1; i < 2000; i += 2) any |= w[i];
    g_is64 = (any == 0) ? 1 : 0;
}

// ---------------- init: h0 = pad(x) (fp32 + packed hi/lo), zero pooled ----------------
__global__ void k_init(const float* __restrict__ x) {
    long gid = (long)blockIdx.x * blockDim.x + threadIdx.x;
    if (gid < 256) g_pooled[gid] = 0.0f;
    if (gid >= (long)NN * 104) return;
    int n = (int)(gid / 104), p = (int)(gid % 104);
    float v0 = 0.f, v1 = 0.f;
    if (p < 50) { v0 = x[n * IND + 2 * p]; v1 = x[n * IND + 2 * p + 1]; }
    if (p < 100) {
        g_h0[(long)n * DD + 2 * p]     = v0;
        g_h0[(long)n * DD + 2 * p + 1] = v1;
    }
    uint32_t hi, lo;
    split_pair(v0, v1, hi, lo);
    g_Ahi[gid] = hi;
    g_Alo[gid] = lo;
}

// ---------------- weight prep ----------------
__global__ void k_prep1(const float* __restrict__ W, const float* __restrict__ w_hh,
                        const float* __restrict__ b_hh) {
    long gid = (long)blockIdx.x * blockDim.x + threadIdx.x;
    const long NP = 4L * 832 * 104;
    if (gid >= NP) {
        long b = gid - NP;
        if (b < 832) g_bias1[b] = (b >= 200 && b < 800) ? b_hh[b - 200] : 0.0f;
        return;
    }
    int p = (int)(gid % 104);
    int n = (int)((gid / 104) % 832);
    int s = (int)(gid / (104L * 832));
    float v0 = 0.f, v1 = 0.f;
    int k0 = 2 * p, k1 = 2 * p + 1;
    if (n < 800 && k0 < 200) {
        if (n < 200) { v0 = W[s * 40000 + k0 * 200 + n]; v1 = W[s * 40000 + k1 * 200 + n]; }
        else         { v0 = w_hh[(n - 200) * 200 + k0];  v1 = w_hh[(n - 200) * 200 + k1]; }
    }
    uint32_t hi, lo;
    split_pair(v0, v1, hi, lo);
    g_B1hi[gid] = hi;
    g_B1lo[gid] = lo;
}

__global__ void k_prep2(const float* __restrict__ w_ih, const float* __restrict__ b_ih) {
    long gid = (long)blockIdx.x * blockDim.x + threadIdx.x;
    const long NP = 640L * 104;
    if (gid >= NP) {
        long b = gid - NP;
        if (b < 640) g_bias2[b] = (b < 600) ? b_ih[b] : 0.0f;
        return;
    }
    int p = (int)(gid % 104);
    int n = (int)(gid / 104);
    float v0 = 0.f, v1 = 0.f;
    if (n < 600 && 2 * p < 200) { v0 = w_ih[n * 200 + 2 * p]; v1 = w_ih[n * 200 + 2 * p + 1]; }
    uint32_t hi, lo;
    split_pair(v0, v1, hi, lo);
    g_B2hi[gid] = hi;
    g_B2lo[gid] = lo;
}

// ---------------- fp32 -> hi/lo bf16 convert (for aggr) ----------------
__global__ void k_convert(const float* __restrict__ src) {
    long gid = (long)blockIdx.x * blockDim.x + threadIdx.x;
    if (gid >= (long)NN * 104) return;
    int n = (int)(gid / 104), p = (int)(gid % 104);
    float v0 = 0.f, v1 = 0.f;
    if (p < 100) { v0 = src[(long)n * DD + 2 * p]; v1 = src[(long)n * DD + 2 * p + 1]; }
    uint32_t hi, lo;
    split_pair(v0, v1, hi, lo);
    g_Ahi[gid] = hi;
    g_Alo[gid] = lo;
}

// ---------------- HMMA GEMM: C[128 x 64-tile] = A[128 x 208] @ B_tile^T ----------------
// A from g_Ahi/g_Alo ([NN][104] u32, k-contig). B image [n][104] u32. 3-product split.
// blockIdx.x = 64-col tile t, blockIdx.y = 128-row block.
// mode 0: col c<200 -> Cm(ld 200), 200<=c<800 -> Cg(ld 600, c-200). mode 1: c<600 -> Cg(ld 600).
__global__ void __launch_bounds__(256)
k_mma(const uint32_t* __restrict__ Bhi, const uint32_t* __restrict__ Blo,
      const float* __restrict__ bias, float* __restrict__ Cm, float* __restrict__ Cg,
      int mode) {
    __shared__ __align__(16) char sm[18432];   // As: 2x128x24 bf16 (12288B) | Bs: 2x64x24 bf16 (6144B)
    const int tid = threadIdx.x;
    const int wid = tid >> 5, lane = tid & 31;
    const int warp_m = wid & 3, warp_n = wid >> 2;
    const int g3 = lane >> 3, l7 = lane & 7;
    const int tcol = blockIdx.x;
    const long row0 = (long)blockIdx.y * 128;

    const uint32_t sbase = smem_u32(sm);

    // ldmatrix addresses (constant across k-chunks)
    uint32_t aaddr[2][2], baddr[2][2];
#pragma unroll
    for (int sp = 0; sp < 2; sp++) {
#pragma unroll
        for (int mi = 0; mi < 2; mi++) {
            int r = warp_m * 32 + mi * 16 + (g3 & 1) * 8 + l7;
            aaddr[sp][mi] = sbase + sp * 6144 + r * 48 + ((g3 >> 1) * 8) * 2;
        }
#pragma unroll
        for (int np = 0; np < 2; np++) {
            int n = warp_n * 32 + np * 16 + (g3 >> 1) * 8 + l7;
            baddr[sp][np] = sbase + 12288 + sp * 3072 + n * 48 + ((g3 & 1) * 8) * 2;
        }
    }

    float acc[2][4][4];
#pragma unroll
    for (int i = 0; i < 2; i++)
#pragma unroll
        for (int j = 0; j < 4; j++)
#pragma unroll
            for (int q = 0; q < 4; q++) acc[i][j][q] = 0.f;

    const uint4* Ah4 = (const uint4*)g_Ahi;
    const uint4* Al4 = (const uint4*)g_Alo;
    const uint4* Bh4 = (const uint4*)Bhi;
    const uint4* Bl4 = (const uint4*)Blo;

    for (int kc = 0; kc < 13; kc++) {
        __syncthreads();
        // A: 512 16B-loads, 2 per thread
#pragma unroll
        for (int i = 0; i < 2; i++) {
            int idx = tid + i * 256;
            int row = idx & 127, rest = idx >> 7;
            int half = rest & 1, sp = rest >> 1;
            long gr = row0 + row;
            uint4 v = make_uint4(0, 0, 0, 0);
            if (gr < NN) v = (sp ? Al4 : Ah4)[gr * 26 + kc * 2 + half];
            *(uint4*)(sm + sp * 6144 + row * 48 + half * 16) = v;
        }
        // B: 256 16B-loads, 1 per thread
        {
            int n = tid & 63, rest = tid >> 6;
            int half = rest & 1, sp = rest >> 1;
            long gn = (long)tcol * 64 + n;
            uint4 v = (sp ? Bl4 : Bh4)[gn * 26 + kc * 2 + half];
            *(uint4*)(sm + 12288 + sp * 3072 + n * 48 + half * 16) = v;
        }
        __syncthreads();

        uint32_t ahi[2][4], alo[2][4], bhi[4][2], blo[4][2];
#pragma unroll
        for (int mi = 0; mi < 2; mi++) {
            LDSM_X4(ahi[mi][0], ahi[mi][1], ahi[mi][2], ahi[mi][3], aaddr[0][mi]);
            LDSM_X4(alo[mi][0], alo[mi][1], alo[mi][2], alo[mi][3], aaddr[1][mi]);
        }
#pragma unroll
        for (int np = 0; np < 2; np++) {
            uint32_t r0, r1, r2, r3;
            LDSM_X4(r0, r1, r2, r3, baddr[0][np]);
            bhi[np * 2][0] = r0; bhi[np * 2][1] = r1;
            bhi[np * 2 + 1][0] = r2; bhi[np * 2 + 1][1] = r3;
            LDSM_X4(r0, r1, r2, r3, baddr[1][np]);
            blo[np * 2][0] = r0; blo[np * 2][1] = r1;
            blo[np * 2 + 1][0] = r2; blo[np * 2 + 1][1] = r3;
        }
#pragma unroll
        for (int mi = 0; mi < 2; mi++)
#pragma unroll
            for (int ni = 0; ni < 4; ni++) {
                MMA_BF16(acc[mi][ni], ahi[mi], bhi[ni]);
                MMA_BF16(acc[mi][ni], ahi[mi], blo[ni]);
                MMA_BF16(acc[mi][ni], alo[mi], bhi[ni]);
            }
    }

    // epilogue
    const int g = lane >> 2, tg = lane & 3;
#pragma unroll
    for (int mi = 0; mi < 2; mi++) {
#pragma unroll
        for (int ni = 0; ni < 4; ni++) {
            int c = tcol * 64 + warp_n * 32 + ni * 8 + tg * 2;
            float bx = bias[c], by = bias[c + 1];
            long r1 = row0 + warp_m * 32 + mi * 16 + g;
            long r2 = r1 + 8;
            float2 p0 = make_float2(acc[mi][ni][0] + bx, acc[mi][ni][1] + by);
            float2 p1 = make_float2(acc[mi][ni][2] + bx, acc[mi][ni][3] + by);
            if (mode == 0) {
                if (c < 200) {
                    if (r1 < NN) *(float2*)(Cm + r1 * 200 + c) = p0;
                    if (r2 < NN) *(float2*)(Cm + r2 * 200 + c) = p1;
                } else if (c < 800) {
                    if (r1 < NN) *(float2*)(Cg + r1 * 600 + (c - 200)) = p0;
                    if (r2 < NN) *(float2*)(Cg + r2 * 600 + (c - 200)) = p1;
                }
            } else {
                if (c < 600) {
                    if (r1 < NN) *(float2*)(Cg + r1 * 600 + c) = p0;
                    if (r2 < NN) *(float2*)(Cg + r2 * 600 + c) = p1;
                }
            }
        }
    }
}

// ---------------- edge scatter-add ----------------
__global__ void k_scatter(const int* __restrict__ ei) {
    int gid = blockIdx.x * blockDim.x + threadIdx.x;
    if (gid >= EE * 50) return;
    int e = gid / 50;
    int q = gid % 50;
    int src, dst;
    if (g_is64) { src = ei[2 * e]; dst = ei[2 * (EE + e)]; }
    else        { src = ei[e];     dst = ei[EE + e]; }
    float4 v = *(const float4*)&g_m[(long)src * DD + 4 * q];
    float* a = &g_aggr[(long)dst * DD + 4 * q];
    atomicAdd(a + 0, v.x);
    atomicAdd(a + 1, v.y);
    atomicAdd(a + 2, v.z);
    atomicAdd(a + 3, v.w);
}

// ---------------- GRU elementwise (fused: also emits packed hi/lo of h_next) ----------------
__device__ __forceinline__ float sigmoidf_(float x) { return 1.0f / (1.0f + expf(-x)); }

__global__ void k_gru(const float* __restrict__ hprev, float* __restrict__ hnext) {
    long gid = (long)blockIdx.x * blockDim.x + threadIdx.x;
    if (gid >= (long)NN * 100) return;
    int n = (int)(gid / 100), p = (int)(gid % 100);
    const float* gi = g_gi + (long)n * GG;
    const float* gh = g_gh + (long)n * GG;
    float h2[2];
#pragma unroll
    for (int j = 0; j < 2; j++) {
        int d = 2 * p + j;
        float r  = sigmoidf_(gi[d] + gh[d]);
        float z  = sigmoidf_(gi[DD + d] + gh[DD + d]);
        float nv = tanhf(gi[2 * DD + d] + r * gh[2 * DD + d]);
        float h  = hprev[(long)n * DD + d];
        h2[j] = (1.0f - z) * nv + z * h;
        hnext[(long)n * DD + d] = h2[j];
    }
    uint32_t hi, lo;
    split_pair(h2[0], h2[1], hi, lo);
    g_Ahi[(long)n * 104 + p] = hi;
    g_Alo[(long)n * 104 + p] = lo;
}

// ---------------- relu + global max pool ----------------
__global__ void k_pool(const float* __restrict__ h) {
    int d = threadIdx.x;
    if (d >= DD) return;
    int n0 = blockIdx.x * 500;
    int n1 = n0 + 500; if (n1 > NN) n1 = NN;
    float v = 0.0f;
    for (int n = n0; n < n1; n++) v = fmaxf(v, h[(long)n * DD + d]);
    atomicMax((int*)&g_pooled[d], __float_as_int(v));
}

// ---------------- classifier + softmax ----------------
__global__ void k_final(const float* __restrict__ cls_w, const float* __restrict__ cls_b,
                        float* __restrict__ out) {
    int lane = threadIdx.x;
    float l0 = 0.0f, l1 = 0.0f;
    for (int d = lane; d < DD; d += 32) {
        float p = g_pooled[d];
        l0 += p * cls_w[d];
        l1 += p * cls_w[DD + d];
    }
#pragma unroll
    for (int o = 16; o; o >>= 1) {
        l0 += __shfl_xor_sync(0xFFFFFFFF, l0, o);
        l1 += __shfl_xor_sync(0xFFFFFFFF, l1, o);
    }
    if (lane == 0) {
        l0 += cls_b[0];
        l1 += cls_b[1];
        float mx = fmaxf(l0, l1);
        float e0 = expf(l0 - mx), e1 = expf(l1 - mx);
        float s = e0 + e1;
        out[0] = e0 / s;
        out[1] = e1 / s;
    }
}

// ---------------- launch ----------------
extern "C" void kernel_launch(void* const* d_in, const int* in_sizes, int n_in,
                              void* d_out, int out_size) {
    const float* x     = (const float*)d_in[0];
    const float* W     = (const float*)d_in[1];
    const float* w_ih  = (const float*)d_in[2];
    const float* w_hh  = (const float*)d_in[3];
    const float* b_ih  = (const float*)d_in[4];
    const float* b_hh  = (const float*)d_in[5];
    const float* cls_w = (const float*)d_in[6];
    const float* cls_b = (const float*)d_in[7];
    const int*   ei    = (const int*)d_in[8];
    float*       out   = (float*)d_out;

    float *h0, *h1, *mp, *aggr, *gi, *gh, *bias1, *bias2;
    uint32_t *b1h, *b1l, *b2h, *b2l;
    cudaGetSymbolAddress((void**)&h0,    g_h0);
    cudaGetSymbolAddress((void**)&h1,    g_h1);
    cudaGetSymbolAddress((void**)&mp,    g_m);
    cudaGetSymbolAddress((void**)&aggr,  g_aggr);
    cudaGetSymbolAddress((void**)&gi,    g_gi);
    cudaGetSymbolAddress((void**)&gh,    g_gh);
    cudaGetSymbolAddress((void**)&bias1, g_bias1);
    cudaGetSymbolAddress((void**)&bias2, g_bias2);
    cudaGetSymbolAddress((void**)&b1h,   g_B1hi);
    cudaGetSymbolAddress((void**)&b1l,   g_B1lo);
    cudaGetSymbolAddress((void**)&b2h,   g_B2hi);
    cudaGetSymbolAddress((void**)&b2l,   g_B2lo);
    float* hb[2] = {h0, h1};

    k_detect<<<1, 1>>>(ei);
    k_init<<<(int)(((long)NN * 104 + 255) / 256), 256>>>(x);
    k_prep1<<<(int)((4L * 832 * 104 + 832 + 255) / 256), 256>>>(W, w_hh, b_hh);
    k_prep2<<<(int)((640L * 104 + 640 + 255) / 256), 256>>>(w_ih, b_ih);

    const int rowBlocks = (NN + 127) / 128;  // 782
    const int cvtBlocks = (int)(((long)NN * 104 + 255) / 256);
    const int gruBlocks = (int)(((long)NN * 100 + 255) / 256);

    for (int s = 0; s < 4; s++) {
        float* hcur = hb[s & 1];
        float* hnxt = hb[(s + 1) & 1];
        cudaMemsetAsync(aggr, 0, (size_t)NN * DD * sizeof(float));
        // [m | gh] = hcur @ [W_s | w_hh^T] (+ [0 | b_hh]); A = packed hcur (from init/gru)
        k_mma<<<dim3(13, rowBlocks), 256>>>(b1h + (size_t)s * 832 * 104,
                                            b1l + (size_t)s * 832 * 104,
                                            bias1, mp, gh, 0);
        k_scatter<<<(EE * 50 + 255) / 256, 256>>>(ei);
        k_convert<<<cvtBlocks, 256>>>(aggr);
        // gi = aggr @ w_ih^T + b_ih
        k_mma<<<dim3(10, rowBlocks), 256>>>(b2h, b2l, bias2, nullptr, gi, 1);
        k_gru<<<gruBlocks, 256>>>(hcur, hnxt);
    }

    k_pool<<<(NN + 499) / 500, 256>>>(hb[0]);
    k_final<<<1, 32>>>(cls_w, cls_b, out);
}